// round 13
// baseline (speedup 1.0000x reference)
#include <cuda_runtime.h>
#include <cuda_bf16.h>
#include <math_constants.h>
#include <cstdint>

#define Bn 2
#define Tn 2048
#define DMn 1024
#define Hn 16
#define DKn 64
#define DVn 64
#define BTn (Bn * Tn)

// Scratch (allocation-free rule: __device__ globals)
__device__ float g_Q[Bn * Hn * Tn * DKn];   // [B,H,T,DK]
__device__ float g_K[Bn * Hn * Tn * DKn];   // [B,H,T,DK]
__device__ float g_V[Bn * Hn * Tn * DVn];   // [B,H,T,DV]
__device__ float g_ctx[BTn * (Hn * DVn)];   // [B*T, H*DV]

// ===========================================================================
// bf16 mma.sync helpers (base PTX, compute_103-safe)
// ===========================================================================
__device__ __forceinline__ uint32_t pack_bf16(float e, float o) {
    __nv_bfloat162 t = __floats2bfloat162_rn(e, o);
    return *(uint32_t*)&t;
}
// bf16 split of a pair: (e,o) -> hi pair + lo pair (x ~ hi + lo)
__device__ __forceinline__ void bf16_split2(float e, float o,
                                            uint32_t& hi, uint32_t& lo) {
    float eh = __bfloat162float(__float2bfloat16_rn(e));
    float oh = __bfloat162float(__float2bfloat16_rn(o));
    hi = pack_bf16(eh, oh);
    lo = pack_bf16(e - eh, o - oh);
}
// D(16x8) += A(16x16 row, bf16x2) * B(16x8 col, bf16x2)
__device__ __forceinline__ void mma16(float* d, const uint32_t* a, const uint32_t* b) {
    asm volatile(
        "mma.sync.aligned.m16n8k16.row.col.f32.bf16.bf16.f32 "
        "{%0,%1,%2,%3}, {%4,%5,%6,%7}, {%8,%9}, {%0,%1,%2,%3};"
        : "+f"(d[0]), "+f"(d[1]), "+f"(d[2]), "+f"(d[3])
        : "r"(a[0]), "r"(a[1]), "r"(a[2]), "r"(a[3]), "r"(b[0]), "r"(b[1]));
}

// ===========================================================================
// 3xBF16 128x64 GEMM body (K=1024, BK=32), 256 threads = 8 warps (4m x 2n)
// Register-prefetch pipeline: next tile loads overlap current tile MMAs.
// ===========================================================================
#define ASTu 20   // A stride in u32 (16 k-pairs + pad)
#define BSTu 72   // B stride in u32 (64 cols + pad)
#define GS_AH 0
#define GS_AL (128 * ASTu)
#define GS_BH (2 * 128 * ASTu)
#define GS_BL (2 * 128 * ASTu + 16 * BSTu)
#define GS_TOT (2 * 128 * ASTu + 2 * 16 * BSTu)   // 7424 u32 = 29696 B

__device__ __forceinline__ void gemm_body3(
    const float* __restrict__ Ag, const float* __restrict__ Bg, int ldb,
    float acc[2][4][4], uint32_t* gs)
{
    uint32_t* Ah = gs + GS_AH;
    uint32_t* Al = gs + GS_AL;
    uint32_t* Bh = gs + GS_BH;
    uint32_t* Bl = gs + GS_BL;

    const int tid  = threadIdx.x;
    const int lane = tid & 31;
    const int wid  = tid >> 5;
    const int gid  = lane >> 2;
    const int tig  = lane & 3;
    const int wm   = (wid >> 1) * 32;
    const int wn   = (wid & 1) * 32;
    const int bkp  = tid >> 4;          // B pair-row 0..15
    const int bc   = (tid & 15) * 4;    // B col

    float4 ra[4];
    float4 rb0, rb1;

    // prologue: load tile k0=0 into registers
    #pragma unroll
    for (int i = 0; i < 4; i++) {
        int lin = tid + i * 256;
        int r = lin >> 3, c = (lin & 7) * 4;
        ra[i] = *(const float4*)(Ag + (size_t)r * DMn + c);
    }
    rb0 = *(const float4*)(Bg + (size_t)(2 * bkp) * ldb + bc);
    rb1 = *(const float4*)(Bg + (size_t)(2 * bkp + 1) * ldb + bc);

    for (int k0 = 0; k0 < DMn; k0 += 32) {
        // store current registers (split + pack) to smem
        #pragma unroll
        for (int i = 0; i < 4; i++) {
            int lin = tid + i * 256;
            int r = lin >> 3, c = (lin & 7) * 4;
            uint32_t h0, l0, h1, l1;
            bf16_split2(ra[i].x, ra[i].y, h0, l0);
            bf16_split2(ra[i].z, ra[i].w, h1, l1);
            *(uint2*)(Ah + r * ASTu + (c >> 1)) = make_uint2(h0, h1);
            *(uint2*)(Al + r * ASTu + (c >> 1)) = make_uint2(l0, l1);
        }
        {
            uint4 h, l;
            bf16_split2(rb0.x, rb1.x, h.x, l.x);
            bf16_split2(rb0.y, rb1.y, h.y, l.y);
            bf16_split2(rb0.z, rb1.z, h.z, l.z);
            bf16_split2(rb0.w, rb1.w, h.w, l.w);
            *(uint4*)(Bh + bkp * BSTu + bc) = h;
            *(uint4*)(Bl + bkp * BSTu + bc) = l;
        }
        __syncthreads();

        // prefetch next tile into registers (overlaps MMAs below)
        if (k0 + 32 < DMn) {
            #pragma unroll
            for (int i = 0; i < 4; i++) {
                int lin = tid + i * 256;
                int r = lin >> 3, c = (lin & 7) * 4;
                ra[i] = *(const float4*)(Ag + (size_t)r * DMn + k0 + 32 + c);
            }
            rb0 = *(const float4*)(Bg + (size_t)(k0 + 32 + 2 * bkp) * ldb + bc);
            rb1 = *(const float4*)(Bg + (size_t)(k0 + 32 + 2 * bkp + 1) * ldb + bc);
        }

        #pragma unroll
        for (int kk = 0; kk < 2; kk++) {          // two k16 steps cover BK=32
            uint32_t ah[2][4], al[2][4];
            #pragma unroll
            for (int m = 0; m < 2; m++) {
                int r0 = (wm + m * 16 + gid) * ASTu + kk * 8 + tig;
                int r1 = (wm + m * 16 + 8 + gid) * ASTu + kk * 8 + tig;
                ah[m][0] = Ah[r0]; ah[m][1] = Ah[r1];
                ah[m][2] = Ah[r0 + 4]; ah[m][3] = Ah[r1 + 4];
                al[m][0] = Al[r0]; al[m][1] = Al[r1];
                al[m][2] = Al[r0 + 4]; al[m][3] = Al[r1 + 4];
            }
            #pragma unroll
            for (int n = 0; n < 4; n++) {
                int b0 = (kk * 8 + tig) * BSTu + wn + n * 8 + gid;
                int b1 = (kk * 8 + 4 + tig) * BSTu + wn + n * 8 + gid;
                uint32_t bh[2] = {Bh[b0], Bh[b1]};
                uint32_t bl[2] = {Bl[b0], Bl[b1]};
                #pragma unroll
                for (int m = 0; m < 2; m++) {
                    mma16(acc[m][n], al[m], bh);
                    mma16(acc[m][n], ah[m], bl);
                    mma16(acc[m][n], ah[m], bh);
                }
            }
        }
        __syncthreads();
    }
}

// ---------------------------------------------------------------------------
// QKV projection: grid (BT/128, H, 3), block 256
// ---------------------------------------------------------------------------
__global__ __launch_bounds__(256, 2) void proj_kernel(
    const float* __restrict__ xq, const float* __restrict__ xk,
    const float* __restrict__ xv, const float* __restrict__ wq,
    const float* __restrict__ wk, const float* __restrict__ wv)
{
    extern __shared__ __align__(16) uint32_t gs[];

    const int which = blockIdx.z;
    const int h     = blockIdx.y;
    const int row0  = blockIdx.x * 128;

    const float* x = which == 0 ? xq : (which == 1 ? xk : xv);
    const float* w = (which == 0 ? wq : (which == 1 ? wk : wv)) + (size_t)h * DMn * DKn;
    float* outp    = which == 0 ? g_Q : (which == 1 ? g_K : g_V);

    float acc[2][4][4] = {};
    gemm_body3(x + (size_t)row0 * DMn, w, DKn, acc, gs);

    const int lane = threadIdx.x & 31;
    const int wid  = threadIdx.x >> 5;
    const int gid  = lane >> 2;
    const int tig  = lane & 3;
    const int wm   = (wid >> 1) * 32;
    const int wn   = (wid & 1) * 32;

    const int b = row0 >> 11;       // 128-row blocks never straddle batch
    #pragma unroll
    for (int m = 0; m < 2; m++) {
        int r = row0 + wm + m * 16 + gid;
        int t = r & 2047;
        size_t base0 = ((size_t)(b * Hn + h) * Tn + t) * DKn;
        size_t base1 = base0 + 8 * DKn;
        #pragma unroll
        for (int n = 0; n < 4; n++) {
            int c = wn + n * 8 + tig * 2;
            *(float2*)(outp + base0 + c) = make_float2(acc[m][n][0], acc[m][n][1]);
            *(float2*)(outp + base1 + c) = make_float2(acc[m][n][2], acc[m][n][3]);
        }
    }
}

// ---------------------------------------------------------------------------
// Output projection: grid (BT/128, DM/64), block 256
// ---------------------------------------------------------------------------
__global__ __launch_bounds__(256, 2) void out_proj_kernel(
    const float* __restrict__ wo, const float* __restrict__ bo,
    float* __restrict__ out)
{
    extern __shared__ __align__(16) uint32_t gs[];

    const int row0 = blockIdx.x * 128;
    const int col0 = blockIdx.y * 64;

    float acc[2][4][4] = {};
    gemm_body3(g_ctx + (size_t)row0 * DMn, wo + col0, DMn, acc, gs);

    const int lane = threadIdx.x & 31;
    const int wid  = threadIdx.x >> 5;
    const int gid  = lane >> 2;
    const int tig  = lane & 3;
    const int wm   = (wid >> 1) * 32;
    const int wn   = (wid & 1) * 32;

    #pragma unroll
    for (int m = 0; m < 2; m++) {
        int r = row0 + wm + m * 16 + gid;
        #pragma unroll
        for (int n = 0; n < 4; n++) {
            int c = col0 + wn + n * 8 + tig * 2;
            float2 bb = *(const float2*)(bo + c);
            *(float2*)(out + (size_t)r * DMn + c) =
                make_float2(acc[m][n][0] + bb.x, acc[m][n][1] + bb.y);
            *(float2*)(out + (size_t)(r + 8) * DMn + c) =
                make_float2(acc[m][n][2] + bb.x, acc[m][n][3] + bb.y);
        }
    }
}

// ---------------------------------------------------------------------------
// Flash attention: QK = 3xBF16 (k16). PV = 3-term bf16 from REGISTERS
// (P C-fragment == A-fragment layout when packed bf16x2; no smem round trip).
// grid (T/64, H, B), block 128 (4 warps); warp owns 16 query rows.
// Keys processed in 64-wide subtiles (sc = 8 n-tiles) to cap registers.
// ---------------------------------------------------------------------------
#define KSTu 36                           // K tile stride in u32 (32 dk-pairs + pad)
#define VSTu 72                           // V tile stride in u32 (64 dv + pad)
#define FS_KH 0
#define FS_KL (128 * KSTu)                // 4608
#define FS_VH (2 * 128 * KSTu)            // 9216
#define FS_VL (FS_VH + 64 * VSTu)         // 13824
#define FS_M  (FS_VL + 64 * VSTu)         // 18432
#define FS_TOT (FS_M + 128)               // 18560 u32 = 74240 B

__global__ __launch_bounds__(128, 3) void flash_kernel(
    const float* __restrict__ mask)
{
    extern __shared__ __align__(16) uint32_t fsu[];
    uint32_t* Kh = fsu + FS_KH;
    uint32_t* Kl = fsu + FS_KL;
    uint32_t* Vh = fsu + FS_VH;
    uint32_t* Vl = fsu + FS_VL;
    float*    Ms = (float*)(fsu + FS_M);

    const int tid  = threadIdx.x;
    const int lane = tid & 31;
    const int wid  = tid >> 5;
    const int gid  = lane >> 2;
    const int tig  = lane & 3;

    const int b  = blockIdx.z;
    const int h  = blockIdx.y;
    const int q0 = blockIdx.x * 64;
    const size_t bh = (size_t)(b * Hn + h);
    const int qr = q0 + wid * 16;

    // Q fragments hi/lo (bf16 pairs): 4 k16 steps over DK=64, register resident
    const float* Qg = g_Q + (bh * Tn + qr) * DKn;
    uint32_t qh[4][4], ql[4][4];
    #pragma unroll
    for (int kk = 0; kk < 4; kk++) {
        float2 e;
        e = *(const float2*)(Qg + gid * DKn + kk * 16 + 2 * tig);
        bf16_split2(e.x, e.y, qh[kk][0], ql[kk][0]);
        e = *(const float2*)(Qg + (gid + 8) * DKn + kk * 16 + 2 * tig);
        bf16_split2(e.x, e.y, qh[kk][1], ql[kk][1]);
        e = *(const float2*)(Qg + gid * DKn + kk * 16 + 2 * tig + 8);
        bf16_split2(e.x, e.y, qh[kk][2], ql[kk][2]);
        e = *(const float2*)(Qg + (gid + 8) * DKn + kk * 16 + 2 * tig + 8);
        bf16_split2(e.x, e.y, qh[kk][3], ql[kk][3]);
    }

    float o[8][4];
    #pragma unroll
    for (int n = 0; n < 8; n++)
        #pragma unroll
        for (int c = 0; c < 4; c++) o[n][c] = 0.0f;

    float m0 = -CUDART_INF_F, m1 = -CUDART_INF_F;
    float l0 = 0.0f, l1 = 0.0f;
    const float inv_dk = 1.0f / 64.0f;

    for (int kt0 = 0; kt0 < Tn; kt0 += 128) {
        __syncthreads();   // K/V tiles free for reuse
        const float* Kg = g_K + (bh * Tn + kt0) * DKn;
        const float* Vg = g_V + (bh * Tn + kt0) * DVn;
        // K tile 128x64: split hi/lo, pack dk-pairs
        #pragma unroll
        for (int i = 0; i < 16; i++) {
            int lin = tid + i * 128;
            int r = lin >> 4, c = (lin & 15) * 4;
            float4 kv = *(const float4*)(Kg + (size_t)r * DKn + c);
            uint32_t h0, l0b, h1, l1b;
            bf16_split2(kv.x, kv.y, h0, l0b);
            bf16_split2(kv.z, kv.w, h1, l1b);
            *(uint2*)(Kh + r * KSTu + (c >> 1)) = make_uint2(h0, h1);
            *(uint2*)(Kl + r * KSTu + (c >> 1)) = make_uint2(l0b, l1b);
        }
        // V tile 128x64: pack KEY-pairs (rows 2p,2p+1) per dv column, hi/lo
        #pragma unroll
        for (int i = 0; i < 8; i++) {
            int lin = tid + i * 128;          // 1024 units: 64 pairs x 16 chunks
            int p = lin >> 4, c = (lin & 15) * 4;
            float4 v0 = *(const float4*)(Vg + (size_t)(2 * p) * DVn + c);
            float4 v1 = *(const float4*)(Vg + (size_t)(2 * p + 1) * DVn + c);
            uint4 hh, ll;
            bf16_split2(v0.x, v1.x, hh.x, ll.x);
            bf16_split2(v0.y, v1.y, hh.y, ll.y);
            bf16_split2(v0.z, v1.z, hh.z, ll.z);
            bf16_split2(v0.w, v1.w, hh.w, ll.w);
            *(uint4*)(Vh + p * VSTu + c) = hh;
            *(uint4*)(Vl + p * VSTu + c) = ll;
        }
        Ms[tid] = mask[b * Tn + kt0 + tid];
        __syncthreads();

        #pragma unroll
        for (int half = 0; half < 2; half++) {
            // ---- S = Q @ K^T over 64-key subtile : 3xBF16 ----
            float sc[8][4];
            #pragma unroll
            for (int n = 0; n < 8; n++)
                #pragma unroll
                for (int c = 0; c < 4; c++) sc[n][c] = 0.0f;
            #pragma unroll
            for (int kk = 0; kk < 4; kk++) {
                #pragma unroll
                for (int n = 0; n < 8; n++) {
                    int base = ((half * 8 + n) * 8 + gid) * KSTu + kk * 8 + tig;
                    uint32_t bh2[2] = {Kh[base], Kh[base + 4]};
                    uint32_t bl2[2] = {Kl[base], Kl[base + 4]};
                    mma16(sc[n], ql[kk], bh2);
                    mma16(sc[n], qh[kk], bl2);
                    mma16(sc[n], qh[kk], bh2);
                }
            }

            // ---- masked scale + faithful zero->-inf quirk + row max ----
            float mx0 = -CUDART_INF_F, mx1 = -CUDART_INF_F;
            #pragma unroll
            for (int n = 0; n < 8; n++) {
                float mk0 = Ms[half * 64 + n * 8 + tig * 2];
                float mk1 = Ms[half * 64 + n * 8 + tig * 2 + 1];
                float s0 = sc[n][0] * inv_dk * mk0; s0 = (s0 == 0.0f) ? -CUDART_INF_F : s0;
                float s1 = sc[n][1] * inv_dk * mk1; s1 = (s1 == 0.0f) ? -CUDART_INF_F : s1;
                float s2 = sc[n][2] * inv_dk * mk0; s2 = (s2 == 0.0f) ? -CUDART_INF_F : s2;
                float s3 = sc[n][3] * inv_dk * mk1; s3 = (s3 == 0.0f) ? -CUDART_INF_F : s3;
                sc[n][0] = s0; sc[n][1] = s1; sc[n][2] = s2; sc[n][3] = s3;
                mx0 = fmaxf(mx0, fmaxf(s0, s1));
                mx1 = fmaxf(mx1, fmaxf(s2, s3));
            }
            mx0 = fmaxf(mx0, __shfl_xor_sync(0xffffffffu, mx0, 1));
            mx0 = fmaxf(mx0, __shfl_xor_sync(0xffffffffu, mx0, 2));
            mx1 = fmaxf(mx1, __shfl_xor_sync(0xffffffffu, mx1, 1));
            mx1 = fmaxf(mx1, __shfl_xor_sync(0xffffffffu, mx1, 2));

            float mn0 = fmaxf(m0, mx0);
            float mn1 = fmaxf(m1, mx1);
            float scale0 = (m0 >= mn0) ? 1.0f : __expf(m0 - mn0);
            float scale1 = (m1 >= mn1) ? 1.0f : __expf(m1 - mn1);

            // ---- exp (in place) + l accumulate ----
            float ls0 = 0.0f, ls1 = 0.0f;
            #pragma unroll
            for (int n = 0; n < 8; n++) {
                float p0 = __expf(sc[n][0] - mn0);
                float p1 = __expf(sc[n][1] - mn0);
                float p2 = __expf(sc[n][2] - mn1);
                float p3 = __expf(sc[n][3] - mn1);
                ls0 += p0 + p1;
                ls1 += p2 + p3;
                sc[n][0] = p0; sc[n][1] = p1; sc[n][2] = p2; sc[n][3] = p3;
            }
            l0 = l0 * scale0 + ls0;
            l1 = l1 * scale1 + ls1;
            m0 = mn0; m1 = mn1;

            // ---- rescale O, then O += P @ V (3-term bf16, P from registers) ----
            #pragma unroll
            for (int n = 0; n < 8; n++) {
                o[n][0] *= scale0; o[n][1] *= scale0;
                o[n][2] *= scale1; o[n][3] *= scale1;
            }
            #pragma unroll
            for (int kk = 0; kk < 4; kk++) {
                // A-fragment for keys kk*16..+15 directly from S C-fragment
                uint32_t pah[4], pal[4];
                bf16_split2(sc[2*kk][0],   sc[2*kk][1],   pah[0], pal[0]);
                bf16_split2(sc[2*kk][2],   sc[2*kk][3],   pah[1], pal[1]);
                bf16_split2(sc[2*kk+1][0], sc[2*kk+1][1], pah[2], pal[2]);
                bf16_split2(sc[2*kk+1][2], sc[2*kk+1][3], pah[3], pal[3]);
                #pragma unroll
                for (int n = 0; n < 8; n++) {
                    int v0 = (half * 32 + kk * 8 + tig) * VSTu + n * 8 + gid;
                    int v1 = (half * 32 + kk * 8 + 4 + tig) * VSTu + n * 8 + gid;
                    uint32_t bh2[2] = {Vh[v0], Vh[v1]};
                    uint32_t bl2[2] = {Vl[v0], Vl[v1]};
                    mma16(o[n], pal, bh2);   // pl*vh
                    mma16(o[n], pah, bl2);   // ph*vl
                    mma16(o[n], pah, bh2);   // ph*vh
                }
            }
        }
    }

    // ---- finalize: row sums across the 4-lane groups, normalize, store ----
    l0 += __shfl_xor_sync(0xffffffffu, l0, 1);
    l0 += __shfl_xor_sync(0xffffffffu, l0, 2);
    l1 += __shfl_xor_sync(0xffffffffu, l1, 1);
    l1 += __shfl_xor_sync(0xffffffffu, l1, 2);
    const float i0 = 1.0f / l0;
    const float i1 = 1.0f / l1;

    float* og0 = g_ctx + (size_t)(b * Tn + qr + gid) * (Hn * DVn) + h * DVn;
    float* og1 = og0 + 8 * (Hn * DVn);
    #pragma unroll
    for (int n = 0; n < 8; n++) {
        *(float2*)(og0 + n * 8 + tig * 2) = make_float2(o[n][0] * i0, o[n][1] * i0);
        *(float2*)(og1 + n * 8 + tig * 2) = make_float2(o[n][2] * i1, o[n][3] * i1);
    }
}

// ---------------------------------------------------------------------------
extern "C" void kernel_launch(void* const* d_in, const int* in_sizes, int n_in,
                              void* d_out, int out_size)
{
    const float* xq   = (const float*)d_in[0];
    const float* xk   = (const float*)d_in[1];
    const float* xv   = (const float*)d_in[2];
    const float* mask = (const float*)d_in[3];
    const float* w_q  = (const float*)d_in[4];
    const float* w_k  = (const float*)d_in[5];
    const float* w_v  = (const float*)d_in[6];
    const float* w_o  = (const float*)d_in[7];
    const float* b_o  = (const float*)d_in[8];
    float* out        = (float*)d_out;

    const int gemm_smem  = GS_TOT * (int)sizeof(uint32_t);   // 29696 B
    const int flash_smem = FS_TOT * (int)sizeof(uint32_t);   // 74240 B
    cudaFuncSetAttribute(proj_kernel,
                         cudaFuncAttributeMaxDynamicSharedMemorySize, gemm_smem);
    cudaFuncSetAttribute(out_proj_kernel,
                         cudaFuncAttributeMaxDynamicSharedMemorySize, gemm_smem);
    cudaFuncSetAttribute(flash_kernel,
                         cudaFuncAttributeMaxDynamicSharedMemorySize, flash_smem);

    dim3 projGrid(BTn / 128, Hn, 3);
    proj_kernel<<<projGrid, 256, gemm_smem>>>(xq, xk, xv, w_q, w_k, w_v);

    dim3 flashGrid(Tn / 64, Hn, Bn);
    flash_kernel<<<flashGrid, 128, flash_smem>>>(mask);

    dim3 outGrid(BTn / 128, DMn / 64);
    out_proj_kernel<<<outGrid, 256, gemm_smem>>>(w_o, b_o, out);
}

// round 14
// speedup vs baseline: 1.0499x; 1.0499x over previous
#include <cuda_runtime.h>
#include <cuda_bf16.h>
#include <math_constants.h>
#include <cstdint>

#define Bn 2
#define Tn 2048
#define DMn 1024
#define Hn 16
#define DKn 64
#define DVn 64
#define BTn (Bn * Tn)

// Scratch (allocation-free rule: __device__ globals)
__device__ float g_Q[Bn * Hn * Tn * DKn];   // [B,H,T,DK]
__device__ float g_K[Bn * Hn * Tn * DKn];   // [B,H,T,DK]
__device__ float g_V[Bn * Hn * Tn * DVn];   // [B,H,T,DV]
__device__ float g_ctx[BTn * (Hn * DVn)];   // [B*T, H*DV]

// ===========================================================================
// bf16 mma.sync helpers (base PTX, compute_103-safe)
// ===========================================================================
__device__ __forceinline__ uint32_t pack_bf16(float e, float o) {
    __nv_bfloat162 t = __floats2bfloat162_rn(e, o);
    return *(uint32_t*)&t;
}
// bf16 split of a pair: (e,o) -> hi pair + lo pair (x ~ hi + lo)
__device__ __forceinline__ void bf16_split2(float e, float o,
                                            uint32_t& hi, uint32_t& lo) {
    float eh = __bfloat162float(__float2bfloat16_rn(e));
    float oh = __bfloat162float(__float2bfloat16_rn(o));
    hi = pack_bf16(eh, oh);
    lo = pack_bf16(e - eh, o - oh);
}
// D(16x8) += A(16x16 row, bf16x2) * B(16x8 col, bf16x2)
__device__ __forceinline__ void mma16(float* d, const uint32_t* a, const uint32_t* b) {
    asm volatile(
        "mma.sync.aligned.m16n8k16.row.col.f32.bf16.bf16.f32 "
        "{%0,%1,%2,%3}, {%4,%5,%6,%7}, {%8,%9}, {%0,%1,%2,%3};"
        : "+f"(d[0]), "+f"(d[1]), "+f"(d[2]), "+f"(d[3])
        : "r"(a[0]), "r"(a[1]), "r"(a[2]), "r"(a[3]), "r"(b[0]), "r"(b[1]));
}

// ===========================================================================
// 3xBF16 128x64 GEMM body (K=1024, BK=32), 256 threads = 8 warps (4m x 2n)
// Term-outer MMA order: same-accumulator MMAs are 8 apart (no dep chains).
// ===========================================================================
#define ASTu 20   // A stride in u32 (16 k-pairs + pad)
#define BSTu 72   // B stride in u32 (64 cols + pad)
#define GS_AH 0
#define GS_AL (128 * ASTu)
#define GS_BH (2 * 128 * ASTu)
#define GS_BL (2 * 128 * ASTu + 16 * BSTu)
#define GS_TOT (2 * 128 * ASTu + 2 * 16 * BSTu)   // 7424 u32 = 29696 B

__device__ __forceinline__ void gemm_body3(
    const float* __restrict__ Ag, const float* __restrict__ Bg, int ldb,
    float acc[2][4][4], uint32_t* gs)
{
    uint32_t* Ah = gs + GS_AH;
    uint32_t* Al = gs + GS_AL;
    uint32_t* Bh = gs + GS_BH;
    uint32_t* Bl = gs + GS_BL;

    const int tid  = threadIdx.x;
    const int lane = tid & 31;
    const int wid  = tid >> 5;
    const int gid  = lane >> 2;
    const int tig  = lane & 3;
    const int wm   = (wid >> 1) * 32;
    const int wn   = (wid & 1) * 32;
    const int bkp  = tid >> 4;          // B pair-row 0..15
    const int bc   = (tid & 15) * 4;    // B col

    for (int k0 = 0; k0 < DMn; k0 += 32) {
        // A tile 128x32: load, split, pack k-pairs
        #pragma unroll
        for (int i = 0; i < 4; i++) {
            int lin = tid + i * 256;
            int r = lin >> 3, c = (lin & 7) * 4;
            float4 v = *(const float4*)(Ag + (size_t)r * DMn + k0 + c);
            uint32_t h0, l0, h1, l1;
            bf16_split2(v.x, v.y, h0, l0);
            bf16_split2(v.z, v.w, h1, l1);
            *(uint2*)(Ah + r * ASTu + (c >> 1)) = make_uint2(h0, h1);
            *(uint2*)(Al + r * ASTu + (c >> 1)) = make_uint2(l0, l1);
        }
        // B tile 32x64
        {
            float4 v0 = *(const float4*)(Bg + (size_t)(k0 + 2 * bkp) * ldb + bc);
            float4 v1 = *(const float4*)(Bg + (size_t)(k0 + 2 * bkp + 1) * ldb + bc);
            uint4 h, l;
            bf16_split2(v0.x, v1.x, h.x, l.x);
            bf16_split2(v0.y, v1.y, h.y, l.y);
            bf16_split2(v0.z, v1.z, h.z, l.z);
            bf16_split2(v0.w, v1.w, h.w, l.w);
            *(uint4*)(Bh + bkp * BSTu + bc) = h;
            *(uint4*)(Bl + bkp * BSTu + bc) = l;
        }
        __syncthreads();

        #pragma unroll
        for (int kk = 0; kk < 2; kk++) {          // two k16 steps cover BK=32
            uint32_t ah[2][4], al[2][4];
            #pragma unroll
            for (int m = 0; m < 2; m++) {
                int r0 = (wm + m * 16 + gid) * ASTu + kk * 8 + tig;
                int r1 = (wm + m * 16 + 8 + gid) * ASTu + kk * 8 + tig;
                ah[m][0] = Ah[r0]; ah[m][1] = Ah[r1];
                ah[m][2] = Ah[r0 + 4]; ah[m][3] = Ah[r1 + 4];
                al[m][0] = Al[r0]; al[m][1] = Al[r1];
                al[m][2] = Al[r0 + 4]; al[m][3] = Al[r1 + 4];
            }
            uint32_t bh[4][2], bl[4][2];
            #pragma unroll
            for (int n = 0; n < 4; n++) {
                int b0 = (kk * 8 + tig) * BSTu + wn + n * 8 + gid;
                int b1 = (kk * 8 + 4 + tig) * BSTu + wn + n * 8 + gid;
                bh[n][0] = Bh[b0]; bh[n][1] = Bh[b1];
                bl[n][0] = Bl[b0]; bl[n][1] = Bl[b1];
            }
            // term-outer: 8 independent MMAs between same-acc reuses
            #pragma unroll
            for (int n = 0; n < 4; n++)
                #pragma unroll
                for (int m = 0; m < 2; m++) mma16(acc[m][n], al[m], bh[n]);
            #pragma unroll
            for (int n = 0; n < 4; n++)
                #pragma unroll
                for (int m = 0; m < 2; m++) mma16(acc[m][n], ah[m], bl[n]);
            #pragma unroll
            for (int n = 0; n < 4; n++)
                #pragma unroll
                for (int m = 0; m < 2; m++) mma16(acc[m][n], ah[m], bh[n]);
        }
        __syncthreads();
    }
}

// ---------------------------------------------------------------------------
// QKV projection: grid (BT/128, H, 3), block 256
// ---------------------------------------------------------------------------
__global__ __launch_bounds__(256, 2) void proj_kernel(
    const float* __restrict__ xq, const float* __restrict__ xk,
    const float* __restrict__ xv, const float* __restrict__ wq,
    const float* __restrict__ wk, const float* __restrict__ wv)
{
    extern __shared__ __align__(16) uint32_t gs[];

    const int which = blockIdx.z;
    const int h     = blockIdx.y;
    const int row0  = blockIdx.x * 128;

    const float* x = which == 0 ? xq : (which == 1 ? xk : xv);
    const float* w = (which == 0 ? wq : (which == 1 ? wk : wv)) + (size_t)h * DMn * DKn;
    float* outp    = which == 0 ? g_Q : (which == 1 ? g_K : g_V);

    float acc[2][4][4] = {};
    gemm_body3(x + (size_t)row0 * DMn, w, DKn, acc, gs);

    const int lane = threadIdx.x & 31;
    const int wid  = threadIdx.x >> 5;
    const int gid  = lane >> 2;
    const int tig  = lane & 3;
    const int wm   = (wid >> 1) * 32;
    const int wn   = (wid & 1) * 32;

    const int b = row0 >> 11;       // 128-row blocks never straddle batch
    #pragma unroll
    for (int m = 0; m < 2; m++) {
        int r = row0 + wm + m * 16 + gid;
        int t = r & 2047;
        size_t base0 = ((size_t)(b * Hn + h) * Tn + t) * DKn;
        size_t base1 = base0 + 8 * DKn;
        #pragma unroll
        for (int n = 0; n < 4; n++) {
            int c = wn + n * 8 + tig * 2;
            *(float2*)(outp + base0 + c) = make_float2(acc[m][n][0], acc[m][n][1]);
            *(float2*)(outp + base1 + c) = make_float2(acc[m][n][2], acc[m][n][3]);
        }
    }
}

// ---------------------------------------------------------------------------
// Output projection: grid (BT/128, DM/64), block 256
// ---------------------------------------------------------------------------
__global__ __launch_bounds__(256, 2) void out_proj_kernel(
    const float* __restrict__ wo, const float* __restrict__ bo,
    float* __restrict__ out)
{
    extern __shared__ __align__(16) uint32_t gs[];

    const int row0 = blockIdx.x * 128;
    const int col0 = blockIdx.y * 64;

    float acc[2][4][4] = {};
    gemm_body3(g_ctx + (size_t)row0 * DMn, wo + col0, DMn, acc, gs);

    const int lane = threadIdx.x & 31;
    const int wid  = threadIdx.x >> 5;
    const int gid  = lane >> 2;
    const int tig  = lane & 3;
    const int wm   = (wid >> 1) * 32;
    const int wn   = (wid & 1) * 32;

    #pragma unroll
    for (int m = 0; m < 2; m++) {
        int r = row0 + wm + m * 16 + gid;
        #pragma unroll
        for (int n = 0; n < 4; n++) {
            int c = col0 + wn + n * 8 + tig * 2;
            float2 bb = *(const float2*)(bo + c);
            *(float2*)(out + (size_t)r * DMn + c) =
                make_float2(acc[m][n][0] + bb.x, acc[m][n][1] + bb.y);
            *(float2*)(out + (size_t)(r + 8) * DMn + c) =
                make_float2(acc[m][n][2] + bb.x, acc[m][n][3] + bb.y);
        }
    }
}

// ---------------------------------------------------------------------------
// Flash attention: QK = 3xBF16 (k16). PV = 3-term bf16 from REGISTERS.
// Term-outer MMA ordering throughout (same-acc MMAs 8 apart).
// grid (T/64, H, B), block 128 (4 warps); warp owns 16 query rows.
// ---------------------------------------------------------------------------
#define KSTu 36                           // K tile stride in u32 (32 dk-pairs + pad)
#define VSTu 72                           // V tile stride in u32 (64 dv + pad)
#define FS_KH 0
#define FS_KL (128 * KSTu)                // 4608
#define FS_VH (2 * 128 * KSTu)            // 9216
#define FS_VL (FS_VH + 64 * VSTu)         // 13824
#define FS_M  (FS_VL + 64 * VSTu)         // 18432
#define FS_TOT (FS_M + 128)               // 18560 u32 = 74240 B

__global__ __launch_bounds__(128, 3) void flash_kernel(
    const float* __restrict__ mask)
{
    extern __shared__ __align__(16) uint32_t fsu[];
    uint32_t* Kh = fsu + FS_KH;
    uint32_t* Kl = fsu + FS_KL;
    uint32_t* Vh = fsu + FS_VH;
    uint32_t* Vl = fsu + FS_VL;
    float*    Ms = (float*)(fsu + FS_M);

    const int tid  = threadIdx.x;
    const int lane = tid & 31;
    const int wid  = tid >> 5;
    const int gid  = lane >> 2;
    const int tig  = lane & 3;

    const int b  = blockIdx.z;
    const int h  = blockIdx.y;
    const int q0 = blockIdx.x * 64;
    const size_t bh = (size_t)(b * Hn + h);
    const int qr = q0 + wid * 16;

    // Q fragments hi/lo (bf16 pairs): 4 k16 steps over DK=64, register resident
    const float* Qg = g_Q + (bh * Tn + qr) * DKn;
    uint32_t qh[4][4], ql[4][4];
    #pragma unroll
    for (int kk = 0; kk < 4; kk++) {
        float2 e;
        e = *(const float2*)(Qg + gid * DKn + kk * 16 + 2 * tig);
        bf16_split2(e.x, e.y, qh[kk][0], ql[kk][0]);
        e = *(const float2*)(Qg + (gid + 8) * DKn + kk * 16 + 2 * tig);
        bf16_split2(e.x, e.y, qh[kk][1], ql[kk][1]);
        e = *(const float2*)(Qg + gid * DKn + kk * 16 + 2 * tig + 8);
        bf16_split2(e.x, e.y, qh[kk][2], ql[kk][2]);
        e = *(const float2*)(Qg + (gid + 8) * DKn + kk * 16 + 2 * tig + 8);
        bf16_split2(e.x, e.y, qh[kk][3], ql[kk][3]);
    }

    float o[8][4];
    #pragma unroll
    for (int n = 0; n < 8; n++)
        #pragma unroll
        for (int c = 0; c < 4; c++) o[n][c] = 0.0f;

    float m0 = -CUDART_INF_F, m1 = -CUDART_INF_F;
    float l0 = 0.0f, l1 = 0.0f;
    const float inv_dk = 1.0f / 64.0f;

    for (int kt0 = 0; kt0 < Tn; kt0 += 128) {
        __syncthreads();   // K/V tiles free for reuse
        const float* Kg = g_K + (bh * Tn + kt0) * DKn;
        const float* Vg = g_V + (bh * Tn + kt0) * DVn;
        // K tile 128x64: split hi/lo, pack dk-pairs
        #pragma unroll
        for (int i = 0; i < 16; i++) {
            int lin = tid + i * 128;
            int r = lin >> 4, c = (lin & 15) * 4;
            float4 kv = *(const float4*)(Kg + (size_t)r * DKn + c);
            uint32_t h0, l0b, h1, l1b;
            bf16_split2(kv.x, kv.y, h0, l0b);
            bf16_split2(kv.z, kv.w, h1, l1b);
            *(uint2*)(Kh + r * KSTu + (c >> 1)) = make_uint2(h0, h1);
            *(uint2*)(Kl + r * KSTu + (c >> 1)) = make_uint2(l0b, l1b);
        }
        // V tile 128x64: pack KEY-pairs (rows 2p,2p+1) per dv column, hi/lo
        #pragma unroll
        for (int i = 0; i < 8; i++) {
            int lin = tid + i * 128;          // 1024 units: 64 pairs x 16 chunks
            int p = lin >> 4, c = (lin & 15) * 4;
            float4 v0 = *(const float4*)(Vg + (size_t)(2 * p) * DVn + c);
            float4 v1 = *(const float4*)(Vg + (size_t)(2 * p + 1) * DVn + c);
            uint4 hh, ll;
            bf16_split2(v0.x, v1.x, hh.x, ll.x);
            bf16_split2(v0.y, v1.y, hh.y, ll.y);
            bf16_split2(v0.z, v1.z, hh.z, ll.z);
            bf16_split2(v0.w, v1.w, hh.w, ll.w);
            *(uint4*)(Vh + p * VSTu + c) = hh;
            *(uint4*)(Vl + p * VSTu + c) = ll;
        }
        Ms[tid] = mask[b * Tn + kt0 + tid];
        __syncthreads();

        #pragma unroll
        for (int half = 0; half < 2; half++) {
            // ---- S = Q @ K^T over 64-key subtile : 3xBF16, term-outer ----
            float sc[8][4];
            #pragma unroll
            for (int n = 0; n < 8; n++)
                #pragma unroll
                for (int c = 0; c < 4; c++) sc[n][c] = 0.0f;
            #pragma unroll
            for (int kk = 0; kk < 4; kk++) {
                uint32_t kbh[8][2], kbl[8][2];
                #pragma unroll
                for (int n = 0; n < 8; n++) {
                    int base = ((half * 8 + n) * 8 + gid) * KSTu + kk * 8 + tig;
                    kbh[n][0] = Kh[base]; kbh[n][1] = Kh[base + 4];
                    kbl[n][0] = Kl[base]; kbl[n][1] = Kl[base + 4];
                }
                #pragma unroll
                for (int n = 0; n < 8; n++) mma16(sc[n], ql[kk], kbh[n]);
                #pragma unroll
                for (int n = 0; n < 8; n++) mma16(sc[n], qh[kk], kbl[n]);
                #pragma unroll
                for (int n = 0; n < 8; n++) mma16(sc[n], qh[kk], kbh[n]);
            }

            // ---- masked scale + faithful zero->-inf quirk + row max ----
            float mx0 = -CUDART_INF_F, mx1 = -CUDART_INF_F;
            #pragma unroll
            for (int n = 0; n < 8; n++) {
                float mk0 = Ms[half * 64 + n * 8 + tig * 2];
                float mk1 = Ms[half * 64 + n * 8 + tig * 2 + 1];
                float s0 = sc[n][0] * inv_dk * mk0; s0 = (s0 == 0.0f) ? -CUDART_INF_F : s0;
                float s1 = sc[n][1] * inv_dk * mk1; s1 = (s1 == 0.0f) ? -CUDART_INF_F : s1;
                float s2 = sc[n][2] * inv_dk * mk0; s2 = (s2 == 0.0f) ? -CUDART_INF_F : s2;
                float s3 = sc[n][3] * inv_dk * mk1; s3 = (s3 == 0.0f) ? -CUDART_INF_F : s3;
                sc[n][0] = s0; sc[n][1] = s1; sc[n][2] = s2; sc[n][3] = s3;
                mx0 = fmaxf(mx0, fmaxf(s0, s1));
                mx1 = fmaxf(mx1, fmaxf(s2, s3));
            }
            mx0 = fmaxf(mx0, __shfl_xor_sync(0xffffffffu, mx0, 1));
            mx0 = fmaxf(mx0, __shfl_xor_sync(0xffffffffu, mx0, 2));
            mx1 = fmaxf(mx1, __shfl_xor_sync(0xffffffffu, mx1, 1));
            mx1 = fmaxf(mx1, __shfl_xor_sync(0xffffffffu, mx1, 2));

            float mn0 = fmaxf(m0, mx0);
            float mn1 = fmaxf(m1, mx1);
            float scale0 = (m0 >= mn0) ? 1.0f : __expf(m0 - mn0);
            float scale1 = (m1 >= mn1) ? 1.0f : __expf(m1 - mn1);

            // ---- exp (in place) + l accumulate ----
            float ls0 = 0.0f, ls1 = 0.0f;
            #pragma unroll
            for (int n = 0; n < 8; n++) {
                float p0 = __expf(sc[n][0] - mn0);
                float p1 = __expf(sc[n][1] - mn0);
                float p2 = __expf(sc[n][2] - mn1);
                float p3 = __expf(sc[n][3] - mn1);
                ls0 += p0 + p1;
                ls1 += p2 + p3;
                sc[n][0] = p0; sc[n][1] = p1; sc[n][2] = p2; sc[n][3] = p3;
            }
            l0 = l0 * scale0 + ls0;
            l1 = l1 * scale1 + ls1;
            m0 = mn0; m1 = mn1;

            // ---- rescale O, then O += P @ V (3-term bf16, term-outer) ----
            #pragma unroll
            for (int n = 0; n < 8; n++) {
                o[n][0] *= scale0; o[n][1] *= scale0;
                o[n][2] *= scale1; o[n][3] *= scale1;
            }
            #pragma unroll
            for (int kk = 0; kk < 4; kk++) {
                // A-fragment for keys kk*16..+15 directly from S C-fragment
                uint32_t pah[4], pal[4];
                bf16_split2(sc[2*kk][0],   sc[2*kk][1],   pah[0], pal[0]);
                bf16_split2(sc[2*kk][2],   sc[2*kk][3],   pah[1], pal[1]);
                bf16_split2(sc[2*kk+1][0], sc[2*kk+1][1], pah[2], pal[2]);
                bf16_split2(sc[2*kk+1][2], sc[2*kk+1][3], pah[3], pal[3]);
                uint32_t vbh[8][2], vbl[8][2];
                #pragma unroll
                for (int n = 0; n < 8; n++) {
                    int v0 = (half * 32 + kk * 8 + tig) * VSTu + n * 8 + gid;
                    int v1 = (half * 32 + kk * 8 + 4 + tig) * VSTu + n * 8 + gid;
                    vbh[n][0] = Vh[v0]; vbh[n][1] = Vh[v1];
                    vbl[n][0] = Vl[v0]; vbl[n][1] = Vl[v1];
                }
                #pragma unroll
                for (int n = 0; n < 8; n++) mma16(o[n], pal, vbh[n]);
                #pragma unroll
                for (int n = 0; n < 8; n++) mma16(o[n], pah, vbl[n]);
                #pragma unroll
                for (int n = 0; n < 8; n++) mma16(o[n], pah, vbh[n]);
            }
        }
    }

    // ---- finalize: row sums across the 4-lane groups, normalize, store ----
    l0 += __shfl_xor_sync(0xffffffffu, l0, 1);
    l0 += __shfl_xor_sync(0xffffffffu, l0, 2);
    l1 += __shfl_xor_sync(0xffffffffu, l1, 1);
    l1 += __shfl_xor_sync(0xffffffffu, l1, 2);
    const float i0 = 1.0f / l0;
    const float i1 = 1.0f / l1;

    float* og0 = g_ctx + (size_t)(b * Tn + qr + gid) * (Hn * DVn) + h * DVn;
    float* og1 = og0 + 8 * (Hn * DVn);
    #pragma unroll
    for (int n = 0; n < 8; n++) {
        *(float2*)(og0 + n * 8 + tig * 2) = make_float2(o[n][0] * i0, o[n][1] * i0);
        *(float2*)(og1 + n * 8 + tig * 2) = make_float2(o[n][2] * i1, o[n][3] * i1);
    }
}

// ---------------------------------------------------------------------------
extern "C" void kernel_launch(void* const* d_in, const int* in_sizes, int n_in,
                              void* d_out, int out_size)
{
    const float* xq   = (const float*)d_in[0];
    const float* xk   = (const float*)d_in[1];
    const float* xv   = (const float*)d_in[2];
    const float* mask = (const float*)d_in[3];
    const float* w_q  = (const float*)d_in[4];
    const float* w_k  = (const float*)d_in[5];
    const float* w_v  = (const float*)d_in[6];
    const float* w_o  = (const float*)d_in[7];
    const float* b_o  = (const float*)d_in[8];
    float* out        = (float*)d_out;

    const int gemm_smem  = GS_TOT * (int)sizeof(uint32_t);   // 29696 B
    const int flash_smem = FS_TOT * (int)sizeof(uint32_t);   // 74240 B
    cudaFuncSetAttribute(proj_kernel,
                         cudaFuncAttributeMaxDynamicSharedMemorySize, gemm_smem);
    cudaFuncSetAttribute(out_proj_kernel,
                         cudaFuncAttributeMaxDynamicSharedMemorySize, gemm_smem);
    cudaFuncSetAttribute(flash_kernel,
                         cudaFuncAttributeMaxDynamicSharedMemorySize, flash_smem);

    dim3 projGrid(BTn / 128, Hn, 3);
    proj_kernel<<<projGrid, 256, gemm_smem>>>(xq, xk, xv, w_q, w_k, w_v);

    dim3 flashGrid(Tn / 64, Hn, Bn);
    flash_kernel<<<flashGrid, 128, flash_smem>>>(mask);

    dim3 outGrid(BTn / 128, DMn / 64);
    out_proj_kernel<<<outGrid, 256, gemm_smem>>>(w_o, b_o, out);
}